// round 2
// baseline (speedup 1.0000x reference)
#include <cuda_runtime.h>
#include <math.h>

#define Bb     8
#define Nn     2048
#define KK     20
#define Pp     64
#define PSZ    32
#define Dd     1024
#define MLPD   2048
#define DEPTHN 6
#define HH     8
#define DHH    64
#define INNERD 512
#define LL     65
#define EPSF   1e-5f

// ------------------------- device scratch -------------------------
__device__ float g_h[(size_t)Bb * Nn * 512];       // concat features [B*N][512]
__device__ float g_xcm[(size_t)Bb * 128 * Nn];     // channel-major copy for KNN
__device__ float g_u[(size_t)Bb * Nn * 256];
__device__ float g_v[(size_t)Bb * Nn * 256];
__device__ int   g_idx[(size_t)Bb * Nn * KK];
__device__ float g_xx[Bb * Nn];
__device__ float g_wdiff[256 * 128];
__device__ float g_sum[1024];
__device__ float g_sumsq[1024];
__device__ float g_y5[(size_t)Bb * Nn * Dd];       // conv5 output
__device__ float g_t[Bb * LL * Dd];                // transformer state
__device__ float g_hn[Bb * LL * Dd];
__device__ float g_qkv[Bb * LL * 3 * INNERD];
__device__ float g_z[Bb * LL * INNERD];
__device__ float g_ff[Bb * LL * MLPD];
__device__ float g_s2[Bb * LL * Dd];

// ------------------------- helpers -------------------------
__global__ void zero_stats_kernel() {
    int t = threadIdx.x;
    g_sum[t] = 0.f;
    g_sumsq[t] = 0.f;
}

// point-major [B*N][C] (row stride ld) -> channel-major g_xcm [B][C][N]
__global__ void transpose_kernel(const float* __restrict__ in, int ld, int C) {
    __shared__ float tile[32][33];
    int b = blockIdx.z;
    int n0 = blockIdx.x * 32, c0 = blockIdx.y * 32;
    int tx = threadIdx.x % 32, ty = threadIdx.x / 32;
    for (int i = ty; i < 32; i += 8) {
        int n = n0 + i, c = c0 + tx;
        tile[i][tx] = (c < C) ? in[((size_t)b * Nn + n) * ld + c] : 0.f;
    }
    __syncthreads();
    for (int i = ty; i < 32; i += 8) {
        int c = c0 + i, n = n0 + tx;
        if (c < C) g_xcm[((size_t)b * C + c) * Nn + n] = tile[tx][i];
    }
}

__global__ void compute_xx_kernel(const float* __restrict__ in, int ld, int C) {
    int i = blockIdx.x * blockDim.x + threadIdx.x;
    if (i < Bb * Nn) {
        const float* p = in + (size_t)i * ld;
        float s = 0.f;
        for (int c = 0; c < C; c++) s += p[c] * p[c];
        g_xx[i] = s;
    }
}

// ------------------------- fused KNN -------------------------
// grid (Nn/16, Bb), 256 threads, dyn smem: xs[16*C] + dist[16*Nn]
__global__ void knn_kernel(int C) {
    extern __shared__ float sm[];
    float* xs = sm;                 // [16][C]
    float* dist = sm + 16 * C;      // [16][Nn]
    int b = blockIdx.y;
    int n0 = blockIdx.x * 16;
    int t = threadIdx.x;
    const float* xb = g_xcm + (size_t)b * C * Nn;

    for (int i = t; i < 16 * C; i += 256) {
        int r = i % 16, c = i / 16;
        xs[r * C + c] = xb[(size_t)c * Nn + n0 + r];
    }
    __syncthreads();

    // distance tile: per thread 16 rows x 4 cols register tile
    for (int half = 0; half < 2; half++) {
        int mb = half * 1024 + t;
        float acc[16][4];
#pragma unroll
        for (int r = 0; r < 16; r++)
#pragma unroll
            for (int q = 0; q < 4; q++) acc[r][q] = 0.f;
        for (int c = 0; c < C; c++) {
            const float* col = xb + (size_t)c * Nn;
            float xm0 = col[mb];
            float xm1 = col[mb + 256];
            float xm2 = col[mb + 512];
            float xm3 = col[mb + 768];
#pragma unroll
            for (int r = 0; r < 16; r++) {
                float xr = xs[r * C + c];
                acc[r][0] += xr * xm0;
                acc[r][1] += xr * xm1;
                acc[r][2] += xr * xm2;
                acc[r][3] += xr * xm3;
            }
        }
#pragma unroll
        for (int q = 0; q < 4; q++) {
            float xxm = g_xx[b * Nn + mb + q * 256];
#pragma unroll
            for (int r = 0; r < 16; r++)
                dist[r * Nn + mb + q * 256] = 2.f * acc[r][q] - xxm;
        }
    }
    __syncthreads();

    // top-20 per row (set semantics; tie -> lowest index)
    int wid = t / 32, lane = t % 32;
    for (int r = wid; r < 16; r += 8) {
        float* drow = dist + r * Nn;
        int n = n0 + r;
        for (int j = 0; j < KK; j++) {
            float bv = -1e30f;
            int bi = 0x7fffffff;
            for (int m = lane; m < Nn; m += 32) {
                float vv = drow[m];
                if (vv > bv) { bv = vv; bi = m; }
            }
            for (int off = 16; off; off >>= 1) {
                float ov = __shfl_down_sync(0xffffffffu, bv, off);
                int   oi = __shfl_down_sync(0xffffffffu, bi, off);
                if (ov > bv || (ov == bv && oi < bi)) { bv = ov; bi = oi; }
            }
            bi = __shfl_sync(0xffffffffu, bi, 0);
            if (lane == 0) g_idx[((size_t)b * Nn + n) * KK + j] = bi;
            drow[bi] = -1e30f;
        }
    }
}

// ------------------------- weight diff -------------------------
__global__ void wdiff_kernel(const float* __restrict__ w, int O, int C) {
    int i = blockIdx.x * blockDim.x + threadIdx.x;
    if (i < O * C) {
        int o = i / C, c = i % C;
        g_wdiff[i] = w[o * 2 * C + C + c] - w[o * 2 * C + c];
    }
}

// ------------------------- generic fp32 GEMM -------------------------
// C[M][N] = A[M][K] * B   (+bias, optional exact GELU)
// TB=true : B is [N][K] (ldb = row stride)   -> A @ B^T
// TB=false: B is [K][N] (ldb = row stride)   -> A @ B
template <bool TB>
__global__ void gemm_kernel(const float* __restrict__ A, int lda,
                            const float* __restrict__ Bm, int ldb,
                            float* __restrict__ Cm, int ldc,
                            int M, int N, int K,
                            const float* __restrict__ bias, int act) {
    __shared__ float As[16][68];
    __shared__ float Bs[16][68];
    int tid = threadIdx.x;
    int tx = tid % 16, ty = tid / 16;
    int m0 = blockIdx.y * 64, n0 = blockIdx.x * 64;
    float acc[4][4];
#pragma unroll
    for (int i = 0; i < 4; i++)
#pragma unroll
        for (int j = 0; j < 4; j++) acc[i][j] = 0.f;

    for (int k0 = 0; k0 < K; k0 += 16) {
#pragma unroll
        for (int i = 0; i < 4; i++) {
            int e = tid + i * 256;
            int r = e / 16, c = e % 16;
            int m = m0 + r, k = k0 + c;
            As[c][r] = (m < M && k < K) ? A[(size_t)m * lda + k] : 0.f;
        }
        if (TB) {
#pragma unroll
            for (int i = 0; i < 4; i++) {
                int e = tid + i * 256;
                int r = e / 16, c = e % 16;
                int n = n0 + r, k = k0 + c;
                Bs[c][r] = (n < N && k < K) ? Bm[(size_t)n * ldb + k] : 0.f;
            }
        } else {
#pragma unroll
            for (int i = 0; i < 4; i++) {
                int e = tid + i * 256;
                int r = e / 64, c = e % 64;
                int k = k0 + r, n = n0 + c;
                Bs[r][c] = (k < K && n < N) ? Bm[(size_t)k * ldb + n] : 0.f;
            }
        }
        __syncthreads();
#pragma unroll
        for (int kk = 0; kk < 16; kk++) {
            float a0 = As[kk][ty * 4 + 0];
            float a1 = As[kk][ty * 4 + 1];
            float a2 = As[kk][ty * 4 + 2];
            float a3 = As[kk][ty * 4 + 3];
            float b0 = Bs[kk][tx * 4 + 0];
            float b1 = Bs[kk][tx * 4 + 1];
            float b2 = Bs[kk][tx * 4 + 2];
            float b3 = Bs[kk][tx * 4 + 3];
            acc[0][0] += a0 * b0; acc[0][1] += a0 * b1; acc[0][2] += a0 * b2; acc[0][3] += a0 * b3;
            acc[1][0] += a1 * b0; acc[1][1] += a1 * b1; acc[1][2] += a1 * b2; acc[1][3] += a1 * b3;
            acc[2][0] += a2 * b0; acc[2][1] += a2 * b1; acc[2][2] += a2 * b2; acc[2][3] += a2 * b3;
            acc[3][0] += a3 * b0; acc[3][1] += a3 * b1; acc[3][2] += a3 * b2; acc[3][3] += a3 * b3;
        }
        __syncthreads();
    }
#pragma unroll
    for (int i = 0; i < 4; i++) {
        int m = m0 + ty * 4 + i;
        if (m >= M) continue;
#pragma unroll
        for (int j = 0; j < 4; j++) {
            int n = n0 + tx * 4 + j;
            if (n >= N) continue;
            float val = acc[i][j];
            if (bias) val += bias[n];
            if (act == 1) val = 0.5f * val * (1.f + erff(val * 0.70710678118654752f));
            Cm[(size_t)m * ldc + n] = val;
        }
    }
}

// ------------------------- edge gather + stats + max -------------------------
// grid Bb*Nn/16, 256 threads; requires O divides 256.
__global__ void edge_gather_kernel(int off, int O) {
    int t = threadIdx.x;
    int o = t % O;
    int nsub = t / O;
    int NPB = 256 / O;
    int base = blockIdx.x * 16;
    int b = base / Nn;
    float s = 0.f, ss = 0.f;
    int iters = 16 / NPB;
    for (int it = 0; it < iters; it++) {
        int gp = base + it * NPB + nsub;
        float vo = g_v[(size_t)gp * O + o];
        const int* ip = &g_idx[(size_t)gp * KK];
        float mx = -1e30f;
#pragma unroll
        for (int j = 0; j < KK; j++) {
            int mi = ip[j];
            float y = g_u[((size_t)b * Nn + mi) * O + o] + vo;
            s += y;
            ss += y * y;
            mx = fmaxf(mx, y);
        }
        g_h[(size_t)gp * 512 + off + o] = mx;
    }
    atomicAdd(&g_sum[o], s);
    atomicAdd(&g_sumsq[o], ss);
}

__global__ void bn_apply_kernel(int off, int O, const float* __restrict__ gamma,
                                const float* __restrict__ beta, float cntinv) {
    int i = blockIdx.x * blockDim.x + threadIdx.x;
    if (i >= Bb * Nn * O) return;
    int o = i % O;
    int p = i / O;
    float mu = g_sum[o] * cntinv;
    float var = g_sumsq[o] * cntinv - mu * mu;
    float vin = g_h[(size_t)p * 512 + off + o];
    float y = (vin - mu) * rsqrtf(var + EPSF) * gamma[o] + beta[o];
    g_h[(size_t)p * 512 + off + o] = (y >= 0.f) ? y : 0.2f * y;
}

// ------------------------- conv5 stats + patch pool -------------------------
__global__ void col_stats_kernel() {
    int d = blockIdx.x * blockDim.x + threadIdx.x;  // gridDim.x*256 == 1024
    int rows = (Bb * Nn) / 32;
    int m0 = blockIdx.y * rows;
    float s = 0.f, ss = 0.f;
    for (int m = m0; m < m0 + rows; m++) {
        float v = g_y5[(size_t)m * Dd + d];
        s += v;
        ss += v * v;
    }
    atomicAdd(&g_sum[d], s);
    atomicAdd(&g_sumsq[d], ss);
}

__global__ void patch_pool_kernel(const float* __restrict__ g5, const float* __restrict__ b5) {
    int bp = blockIdx.x;
    int b = bp / Pp, p = bp % Pp;
    float cntinv = 1.f / (float)(Bb * Nn);
    for (int d = threadIdx.x; d < Dd; d += 256) {
        float mu = g_sum[d] * cntinv;
        float var = g_sumsq[d] * cntinv - mu * mu;
        float sc = rsqrtf(var + EPSF) * g5[d];
        float bo = b5[d] - mu * sc;
        float mx = -1e30f;
        for (int s = 0; s < PSZ; s++) {
            float v = g_y5[((size_t)b * Nn + p * PSZ + s) * Dd + d];
            mx = fmaxf(mx, v);
        }
        float val = mx * sc + bo;
        val = (val >= 0.f) ? val : 0.2f * val;
        g_t[((size_t)b * LL + 1 + p) * Dd + d] = val;
    }
}

__global__ void cls_init_kernel(const float* __restrict__ cls) {
    int b = blockIdx.x;
    for (int d = threadIdx.x; d < Dd; d += 256)
        g_t[((size_t)b * LL) * Dd + d] = cls[d];
}

// ------------------------- transformer elementwise -------------------------
__global__ void add_pos_kernel(const float* __restrict__ pos) {
    int i = blockIdx.x * blockDim.x + threadIdx.x;
    if (i < Bb * LL * Dd) g_t[i] += pos[i];
}

__global__ void resid_kernel() {
    int i = blockIdx.x * blockDim.x + threadIdx.x;
    if (i < Bb * LL * Dd) g_t[i] += g_s2[i];
}

__global__ void ln_kernel(const float* __restrict__ in, float* __restrict__ out,
                          const float* __restrict__ gg, const float* __restrict__ bbv) {
    int row = blockIdx.x;
    const float* p = in + (size_t)row * Dd;
    float s = 0.f, ss = 0.f;
    for (int d = threadIdx.x; d < Dd; d += 256) {
        float v = p[d];
        s += v;
        ss += v * v;
    }
    __shared__ float red[2][8];
    int lane = threadIdx.x & 31, wid = threadIdx.x >> 5;
    for (int off = 16; off; off >>= 1) {
        s += __shfl_down_sync(0xffffffffu, s, off);
        ss += __shfl_down_sync(0xffffffffu, ss, off);
    }
    if (!lane) { red[0][wid] = s; red[1][wid] = ss; }
    __syncthreads();
    __shared__ float mu_s, rs_s;
    if (threadIdx.x == 0) {
        float S = 0.f, SS = 0.f;
        for (int i = 0; i < 8; i++) { S += red[0][i]; SS += red[1][i]; }
        float mu = S / Dd;
        float var = SS / Dd - mu * mu;
        mu_s = mu;
        rs_s = rsqrtf(var + EPSF);
    }
    __syncthreads();
    float mu = mu_s, r = rs_s;
    for (int d = threadIdx.x; d < Dd; d += 256)
        out[(size_t)row * Dd + d] = (p[d] - mu) * r * gg[d] + bbv[d];
}

// ------------------------- attention -------------------------
// grid 64 (= B*H), 256 threads. dyn smem: q[65*64] k[65*65] v[65*65] p[8*66]
__global__ void attn_kernel() {
    extern __shared__ float sm[];
    float* qs = sm;
    float* ks = qs + 65 * 64;
    float* vs = ks + 65 * 65;
    float* pb = vs + 65 * 65;
    int b = blockIdx.x / HH, h = blockIdx.x % HH;
    int t = threadIdx.x, wid = t / 32, lane = t % 32;
    for (int i = t; i < 65 * 64; i += 256) {
        int l = i / 64, d = i % 64;
        size_t base = ((size_t)(b * LL + l)) * (3 * INNERD) + h * DHH + d;
        qs[l * 64 + d] = g_qkv[base];
        ks[l * 65 + d] = g_qkv[base + INNERD];
        vs[l * 65 + d] = g_qkv[base + 2 * INNERD];
    }
    __syncthreads();
    const float scale = 0.125f;
    for (int l = wid; l < LL; l += 8) {
        float lmax = -1e30f;
        for (int m = lane; m < LL; m += 32) {
            float acc = 0.f;
#pragma unroll 8
            for (int d = 0; d < 64; d++) acc += qs[l * 64 + d] * ks[m * 65 + d];
            acc *= scale;
            pb[wid * 66 + m] = acc;
            lmax = fmaxf(lmax, acc);
        }
        for (int off = 16; off; off >>= 1)
            lmax = fmaxf(lmax, __shfl_xor_sync(0xffffffffu, lmax, off));
        float lsum = 0.f;
        for (int m = lane; m < LL; m += 32) {
            float e = expf(pb[wid * 66 + m] - lmax);
            pb[wid * 66 + m] = e;
            lsum += e;
        }
        for (int off = 16; off; off >>= 1)
            lsum += __shfl_xor_sync(0xffffffffu, lsum, off);
        float inv = 1.f / lsum;
        for (int d = lane; d < 64; d += 32) {
            float acc = 0.f;
            for (int m = 0; m < LL; m++) acc += pb[wid * 66 + m] * vs[m * 65 + d];
            g_z[((size_t)(b * LL + l)) * INNERD + h * DHH + d] = acc * inv;
        }
    }
}

__global__ void copy_out_kernel(float* __restrict__ out) {
    int i = blockIdx.x * blockDim.x + threadIdx.x;
    if (i < Bb * Pp * Dd) {
        int d = i % Dd;
        int bp = i / Dd;
        int b = bp / Pp, p = bp % Pp;
        out[i] = g_t[((size_t)b * LL + 1 + p) * Dd + d];
    }
}

// ------------------------- host orchestration -------------------------
extern "C" void kernel_launch(void* const* d_in, const int* in_sizes, int n_in,
                              void* d_out, int out_size) {
    const float* x    = (const float*)d_in[0];
    const float* pos  = (const float*)d_in[1];
    const float* w1   = (const float*)d_in[2];
    const float* g1   = (const float*)d_in[3];
    const float* b1   = (const float*)d_in[4];
    const float* w2   = (const float*)d_in[5];
    const float* g2   = (const float*)d_in[6];
    const float* b2   = (const float*)d_in[7];
    const float* w3   = (const float*)d_in[8];
    const float* g3   = (const float*)d_in[9];
    const float* b3   = (const float*)d_in[10];
    const float* w4   = (const float*)d_in[11];
    const float* g4   = (const float*)d_in[12];
    const float* b4   = (const float*)d_in[13];
    const float* w5   = (const float*)d_in[14];
    const float* g5   = (const float*)d_in[15];
    const float* b5   = (const float*)d_in[16];
    const float* cls  = (const float*)d_in[17];
    const float* ln1g = (const float*)d_in[18];
    const float* ln1b = (const float*)d_in[19];
    const float* wqkv = (const float*)d_in[20];
    const float* wout = (const float*)d_in[21];
    const float* bout = (const float*)d_in[22];
    const float* ln2g = (const float*)d_in[23];
    const float* ln2b = (const float*)d_in[24];
    const float* wff1 = (const float*)d_in[25];
    const float* bff1 = (const float*)d_in[26];
    const float* wff2 = (const float*)d_in[27];
    const float* bff2 = (const float*)d_in[28];

    float *p_h, *p_u, *p_v, *p_wdiff, *p_y5, *p_t, *p_hn, *p_qkv, *p_z, *p_ff, *p_s2;
    cudaGetSymbolAddress((void**)&p_h, g_h);
    cudaGetSymbolAddress((void**)&p_u, g_u);
    cudaGetSymbolAddress((void**)&p_v, g_v);
    cudaGetSymbolAddress((void**)&p_wdiff, g_wdiff);
    cudaGetSymbolAddress((void**)&p_y5, g_y5);
    cudaGetSymbolAddress((void**)&p_t, g_t);
    cudaGetSymbolAddress((void**)&p_hn, g_hn);
    cudaGetSymbolAddress((void**)&p_qkv, g_qkv);
    cudaGetSymbolAddress((void**)&p_z, g_z);
    cudaGetSymbolAddress((void**)&p_ff, g_ff);
    cudaGetSymbolAddress((void**)&p_s2, g_s2);

    cudaFuncSetAttribute(knn_kernel, cudaFuncAttributeMaxDynamicSharedMemorySize,
                         16 * 128 * 4 + 16 * Nn * 4);
    cudaFuncSetAttribute(attn_kernel, cudaFuncAttributeMaxDynamicSharedMemorySize,
                         (65 * 64 + 2 * 65 * 65 + 8 * 66) * 4);

    auto gemm_nt = [&](const float* A, int lda, const float* Bp, int ldb, float* Cp,
                       int ldc, int M, int N, int K, const float* bias, int act) {
        dim3 g((N + 63) / 64, (M + 63) / 64);
        gemm_kernel<true><<<g, 256>>>(A, lda, Bp, ldb, Cp, ldc, M, N, K, bias, act);
    };
    auto gemm_nn = [&](const float* A, int lda, const float* Bp, int ldb, float* Cp,
                       int ldc, int M, int N, int K, const float* bias, int act) {
        dim3 g((N + 63) / 64, (M + 63) / 64);
        gemm_kernel<false><<<g, 256>>>(A, lda, Bp, ldb, Cp, ldc, M, N, K, bias, act);
    };

    auto edgeconv = [&](const float* xin, int ld, int C, int O, const float* w,
                        const float* gamma, const float* beta, int off) {
        dim3 tg(Nn / 32, (C + 31) / 32, Bb);
        transpose_kernel<<<tg, 256>>>(xin, ld, C);
        compute_xx_kernel<<<(Bb * Nn + 255) / 256, 256>>>(xin, ld, C);
        size_t smem = (size_t)16 * C * 4 + (size_t)16 * Nn * 4;
        knn_kernel<<<dim3(Nn / 16, Bb), 256, smem>>>(C);
        wdiff_kernel<<<(O * C + 255) / 256, 256>>>(w, O, C);
        gemm_nt(xin, ld, w, 2 * C, p_u, O, Bb * Nn, O, C, nullptr, 0);
        gemm_nt(xin, ld, p_wdiff, C, p_v, O, Bb * Nn, O, C, nullptr, 0);
        zero_stats_kernel<<<1, 1024>>>();
        edge_gather_kernel<<<Bb * Nn / 16, 256>>>(off, O);
        bn_apply_kernel<<<(Bb * Nn * O + 255) / 256, 256>>>(
            off, O, gamma, beta, 1.f / ((float)Bb * Nn * KK));
    };

    // ---- DGCNN encoder ----
    edgeconv(x, 3, 3, 64, w1, g1, b1, 0);
    edgeconv(p_h + 0, 512, 64, 64, w2, g2, b2, 64);
    edgeconv(p_h + 64, 512, 64, 128, w3, g3, b3, 128);
    edgeconv(p_h + 128, 512, 128, 256, w4, g4, b4, 256);

    // ---- conv5 + BN + leaky + patch max-pool ----
    gemm_nt(p_h, 512, w5, 512, p_y5, Dd, Bb * Nn, Dd, 512, nullptr, 0);
    zero_stats_kernel<<<1, 1024>>>();
    col_stats_kernel<<<dim3(Dd / 256, 32), 256>>>();
    patch_pool_kernel<<<Bb * Pp, 256>>>(g5, b5);
    cls_init_kernel<<<Bb, 256>>>(cls);

    // ---- transformer ----
    const int M = Bb * LL;        // 520
    const int nel = Bb * LL * Dd;
    for (int i = 0; i < DEPTHN; i++) {
        add_pos_kernel<<<(nel + 255) / 256, 256>>>(pos);
        ln_kernel<<<M, 256>>>(p_t, p_hn, ln1g + i * Dd, ln1b + i * Dd);
        gemm_nn(p_hn, Dd, wqkv + (size_t)i * Dd * 3 * INNERD, 3 * INNERD, p_qkv,
                3 * INNERD, M, 3 * INNERD, Dd, nullptr, 0);
        attn_kernel<<<Bb * HH, 256, (65 * 64 + 2 * 65 * 65 + 8 * 66) * 4>>>();
        gemm_nn(p_z, INNERD, wout + (size_t)i * INNERD * Dd, Dd, p_s2, Dd, M, Dd,
                INNERD, bout + i * Dd, 0);
        resid_kernel<<<(nel + 255) / 256, 256>>>();
        ln_kernel<<<M, 256>>>(p_t, p_hn, ln2g + i * Dd, ln2b + i * Dd);
        gemm_nn(p_hn, Dd, wff1 + (size_t)i * Dd * MLPD, MLPD, p_ff, MLPD, M, MLPD,
                Dd, bff1 + i * MLPD, 1 /*gelu*/);
        gemm_nn(p_ff, MLPD, wff2 + (size_t)i * MLPD * Dd, Dd, p_s2, Dd, M, Dd,
                MLPD, bff2 + i * Dd, 0);
        resid_kernel<<<(nel + 255) / 256, 256>>>();
    }

    copy_out_kernel<<<(Bb * Pp * Dd + 255) / 256, 256>>>((float*)d_out);
}

// round 6
// speedup vs baseline: 1.0065x; 1.0065x over previous
#include <cuda_runtime.h>
#include <math.h>
#include <stdint.h>

#define Bb     8
#define Nn     2048
#define KK     20
#define Pp     64
#define PSZ    32
#define Dd     1024
#define MLPD   2048
#define DEPTHN 6
#define HH     8
#define DHH    64
#define INNERD 512
#define LL     65
#define EPSF   1e-5f

// ------------------------- device scratch -------------------------
__device__ float g_h[(size_t)Bb * Nn * 512];       // concat features [B*N][512]
__device__ float g_xcm[(size_t)Bb * 128 * Nn];     // channel-major copy for KNN
__device__ float g_u[(size_t)Bb * Nn * 256];
__device__ float g_v[(size_t)Bb * Nn * 256];
__device__ int   g_idx[(size_t)Bb * Nn * KK];
__device__ float g_xx[Bb * Nn];
__device__ float g_wdiff[256 * 128];
__device__ float g_sum[1024];
__device__ float g_sumsq[1024];
__device__ float g_y5[(size_t)Bb * Nn * Dd];       // conv5 output
__device__ float g_t[Bb * LL * Dd];                // transformer state
__device__ float g_hn[Bb * LL * Dd];
__device__ float g_qkv[Bb * LL * 3 * INNERD];
__device__ float g_z[Bb * LL * INNERD];
__device__ float g_ff[Bb * LL * MLPD];
__device__ float g_s2[Bb * LL * Dd];

// ------------------------- helpers -------------------------
__global__ void zero_stats_kernel() {
    int t = threadIdx.x;
    g_sum[t] = 0.f;
    g_sumsq[t] = 0.f;
}

// point-major [B*N][C] (row stride ld) -> channel-major g_xcm [B][C][N]
__global__ void transpose_kernel(const float* __restrict__ in, int ld, int C) {
    __shared__ float tile[32][33];
    int b = blockIdx.z;
    int n0 = blockIdx.x * 32, c0 = blockIdx.y * 32;
    int tx = threadIdx.x % 32, ty = threadIdx.x / 32;
    for (int i = ty; i < 32; i += 8) {
        int n = n0 + i, c = c0 + tx;
        tile[i][tx] = (c < C) ? in[((size_t)b * Nn + n) * ld + c] : 0.f;
    }
    __syncthreads();
    for (int i = ty; i < 32; i += 8) {
        int c = c0 + i, n = n0 + tx;
        if (c < C) g_xcm[((size_t)b * C + c) * Nn + n] = tile[tx][i];
    }
}

__global__ void compute_xx_kernel(const float* __restrict__ in, int ld, int C) {
    int i = blockIdx.x * blockDim.x + threadIdx.x;
    if (i < Bb * Nn) {
        const float* p = in + (size_t)i * ld;
        float s = 0.f;
        for (int c = 0; c < C; c++) s += p[c] * p[c];
        g_xx[i] = s;
    }
}

// ------------------------- fused KNN -------------------------
// grid (Nn/16, Bb), 256 threads, dyn smem: xs[16*C] + dist[16*Nn]
__global__ void knn_kernel(int C) {
    extern __shared__ float sm[];
    float* xs = sm;                 // [16][C]
    float* dist = sm + 16 * C;      // [16][Nn]
    int b = blockIdx.y;
    int n0 = blockIdx.x * 16;
    int t = threadIdx.x;
    const float* xb = g_xcm + (size_t)b * C * Nn;

    for (int i = t; i < 16 * C; i += 256) {
        int r = i % 16, c = i / 16;
        xs[r * C + c] = xb[(size_t)c * Nn + n0 + r];
    }
    __syncthreads();

    for (int half = 0; half < 2; half++) {
        int mb = half * 1024 + t;
        float acc[16][4];
#pragma unroll
        for (int r = 0; r < 16; r++)
#pragma unroll
            for (int q = 0; q < 4; q++) acc[r][q] = 0.f;
        for (int c = 0; c < C; c++) {
            const float* col = xb + (size_t)c * Nn;
            float xm0 = col[mb];
            float xm1 = col[mb + 256];
            float xm2 = col[mb + 512];
            float xm3 = col[mb + 768];
#pragma unroll
            for (int r = 0; r < 16; r++) {
                float xr = xs[r * C + c];
                acc[r][0] += xr * xm0;
                acc[r][1] += xr * xm1;
                acc[r][2] += xr * xm2;
                acc[r][3] += xr * xm3;
            }
        }
#pragma unroll
        for (int q = 0; q < 4; q++) {
            float xxm = g_xx[b * Nn + mb + q * 256];
#pragma unroll
            for (int r = 0; r < 16; r++)
                dist[r * Nn + mb + q * 256] = 2.f * acc[r][q] - xxm;
        }
    }
    __syncthreads();

    // top-20 per row (set semantics; tie -> lowest index)
    int wid = t / 32, lane = t % 32;
    for (int r = wid; r < 16; r += 8) {
        float* drow = dist + r * Nn;
        int n = n0 + r;
        for (int j = 0; j < KK; j++) {
            float bv = -1e30f;
            int bi = 0x7fffffff;
            for (int m = lane; m < Nn; m += 32) {
                float vv = drow[m];
                if (vv > bv) { bv = vv; bi = m; }
            }
            for (int off = 16; off; off >>= 1) {
                float ov = __shfl_down_sync(0xffffffffu, bv, off);
                int   oi = __shfl_down_sync(0xffffffffu, bi, off);
                if (ov > bv || (ov == bv && oi < bi)) { bv = ov; bi = oi; }
            }
            bi = __shfl_sync(0xffffffffu, bi, 0);
            if (lane == 0) g_idx[((size_t)b * Nn + n) * KK + j] = bi;
            drow[bi] = -1e30f;
        }
    }
}

// ------------------------- weight diff -------------------------
__global__ void wdiff_kernel(const float* __restrict__ w, int O, int C) {
    int i = blockIdx.x * blockDim.x + threadIdx.x;
    if (i < O * C) {
        int o = i / C, c = i % C;
        g_wdiff[i] = w[o * 2 * C + C + c] - w[o * 2 * C + c];
    }
}

// ------------------------- 3xTF32 tensor-core GEMM -------------------------
// C[M][N] = A[M][K] * B   (+bias, optional exact GELU), fp32-equivalent
// precision via hi/lo tf32 split: d += a_lo*b_hi + a_hi*b_lo + a_hi*b_hi.
// TB=true : B is [N][K] -> A @ B^T ;  TB=false: B is [K][N] -> A @ B
// CTA tile 64x128, KB=32, 8 warps (2x4), warp tile 32x32.
#define BM 64
#define BN 128
#define KB 32
#define LDA_S 36
#define LDB_S 133
// dynamic smem: hi+lo tiles
#define GEMM_SMEM ((BM * LDA_S + KB * LDB_S) * 2 * 4)

__device__ __forceinline__ uint32_t f2tf32(float v) {
    uint32_t r;
    asm("cvt.rna.tf32.f32 %0, %1;" : "=r"(r) : "f"(v));
    return r;
}

__device__ __forceinline__ void mma_tf32(float* d, const uint32_t* a, const uint32_t* b) {
    asm volatile(
        "mma.sync.aligned.m16n8k8.row.col.f32.tf32.tf32.f32 "
        "{%0,%1,%2,%3}, {%4,%5,%6,%7}, {%8,%9}, {%0,%1,%2,%3};"
        : "+f"(d[0]), "+f"(d[1]), "+f"(d[2]), "+f"(d[3])
        : "r"(a[0]), "r"(a[1]), "r"(a[2]), "r"(a[3]), "r"(b[0]), "r"(b[1]));
}

template <bool TB>
__global__ __launch_bounds__(256, 2) void gemm_tf32_kernel(
    const float* __restrict__ A, int lda,
    const float* __restrict__ Bm, int ldb,
    float* __restrict__ Cm, int ldc,
    int M, int N, int K,
    const float* __restrict__ bias, int act) {
    extern __shared__ uint32_t smg[];
    uint32_t* AsH = smg;                                  // [BM][LDA_S]
    uint32_t* AsL = AsH + BM * LDA_S;
    uint32_t* BsH = AsL + BM * LDA_S;                     // [KB][LDB_S]
    uint32_t* BsL = BsH + KB * LDB_S;
    int tid = threadIdx.x;
    int warp = tid >> 5, lane = tid & 31;
    int wm = warp >> 2;          // 0..1
    int wn = warp & 3;           // 0..3
    int g = lane >> 2, tg = lane & 3;
    int m0 = blockIdx.y * BM, n0 = blockIdx.x * BN;

    float acc[2][4][4];
#pragma unroll
    for (int mi = 0; mi < 2; mi++)
#pragma unroll
        for (int ni = 0; ni < 4; ni++)
#pragma unroll
            for (int q = 0; q < 4; q++) acc[mi][ni][q] = 0.f;

    for (int k0 = 0; k0 < K; k0 += KB) {
        // A tile: 64x32, 8 elems/thread, lane <-> k (coalesced)
#pragma unroll
        for (int i = 0; i < 8; i++) {
            int e = tid + i * 256;
            int r = e >> 5, c = e & 31;
            int m = m0 + r, k = k0 + c;
            float v = (m < M && k < K) ? A[(size_t)m * lda + k] : 0.f;
            uint32_t hi = f2tf32(v);
            AsH[r * LDA_S + c] = hi;
            AsL[r * LDA_S + c] = f2tf32(v - __uint_as_float(hi));
        }
        // B tile -> Bs[k][n]
        if (TB) {
#pragma unroll
            for (int i = 0; i < 16; i++) {
                int e = tid + i * 256;
                int k = e & 31, n = e >> 5;   // lane <-> k (coalesced along K)
                int gn = n0 + n, gk = k0 + k;
                float v = (gn < N && gk < K) ? Bm[(size_t)gn * ldb + gk] : 0.f;
                uint32_t hi = f2tf32(v);
                BsH[k * LDB_S + n] = hi;
                BsL[k * LDB_S + n] = f2tf32(v - __uint_as_float(hi));
            }
        } else {
#pragma unroll
            for (int i = 0; i < 16; i++) {
                int e = tid + i * 256;
                int n = e & 127, k = e >> 7;  // lane <-> n (coalesced along N)
                int gn = n0 + n, gk = k0 + k;
                float v = (gn < N && gk < K) ? Bm[(size_t)gk * ldb + gn] : 0.f;
                uint32_t hi = f2tf32(v);
                BsH[k * LDB_S + n] = hi;
                BsL[k * LDB_S + n] = f2tf32(v - __uint_as_float(hi));
            }
        }
        __syncthreads();
#pragma unroll
        for (int ks = 0; ks < 4; ks++) {
            int kk = ks * 8;
            uint32_t aH[2][4], aL[2][4], bH[4][2], bL[4][2];
#pragma unroll
            for (int mi = 0; mi < 2; mi++) {
                int mb = wm * 32 + mi * 16;
                aH[mi][0] = AsH[(mb + g) * LDA_S + kk + tg];
                aH[mi][1] = AsH[(mb + g + 8) * LDA_S + kk + tg];
                aH[mi][2] = AsH[(mb + g) * LDA_S + kk + tg + 4];
                aH[mi][3] = AsH[(mb + g + 8) * LDA_S + kk + tg + 4];
                aL[mi][0] = AsL[(mb + g) * LDA_S + kk + tg];
                aL[mi][1] = AsL[(mb + g + 8) * LDA_S + kk + tg];
                aL[mi][2] = AsL[(mb + g) * LDA_S + kk + tg + 4];
                aL[mi][3] = AsL[(mb + g + 8) * LDA_S + kk + tg + 4];
            }
#pragma unroll
            for (int ni = 0; ni < 4; ni++) {
                int nb = wn * 32 + ni * 8;
                bH[ni][0] = BsH[(kk + tg) * LDB_S + nb + g];
                bH[ni][1] = BsH[(kk + tg + 4) * LDB_S + nb + g];
                bL[ni][0] = BsL[(kk + tg) * LDB_S + nb + g];
                bL[ni][1] = BsL[(kk + tg + 4) * LDB_S + nb + g];
            }
#pragma unroll
            for (int mi = 0; mi < 2; mi++)
#pragma unroll
                for (int ni = 0; ni < 4; ni++) {
                    mma_tf32(acc[mi][ni], aL[mi], bH[ni]);
                    mma_tf32(acc[mi][ni], aH[mi], bL[ni]);
                    mma_tf32(acc[mi][ni], aH[mi], bH[ni]);
                }
        }
        __syncthreads();
    }

    // epilogue
#pragma unroll
    for (int mi = 0; mi < 2; mi++) {
#pragma unroll
        for (int ni = 0; ni < 4; ni++) {
            int col = n0 + wn * 32 + ni * 8 + tg * 2;
#pragma unroll
            for (int hf = 0; hf < 2; hf++) {
                int row = m0 + wm * 32 + mi * 16 + g + hf * 8;
                if (row >= M) continue;
#pragma unroll
                for (int q = 0; q < 2; q++) {
                    int c = col + q;
                    if (c >= N) continue;
                    float val = acc[mi][ni][hf * 2 + q];
                    if (bias) val += bias[c];
                    if (act == 1) val = 0.5f * val * (1.f + erff(val * 0.70710678118654752f));
                    Cm[(size_t)row * ldc + c] = val;
                }
            }
        }
    }
}

// ------------------------- edge gather + stats + max -------------------------
// grid Bb*Nn/16, 256 threads; requires O divides 256.
__global__ void edge_gather_kernel(int off, int O) {
    int t = threadIdx.x;
    int o = t % O;
    int nsub = t / O;
    int NPB = 256 / O;
    int base = blockIdx.x * 16;
    int b = base / Nn;
    float s = 0.f, ss = 0.f;
    int iters = 16 / NPB;
    for (int it = 0; it < iters; it++) {
        int gp = base + it * NPB + nsub;
        float vo = g_v[(size_t)gp * O + o];
        const int* ip = &g_idx[(size_t)gp * KK];
        float mx = -1e30f;
#pragma unroll
        for (int j = 0; j < KK; j++) {
            int mi = ip[j];
            float y = g_u[((size_t)b * Nn + mi) * O + o] + vo;
            s += y;
            ss += y * y;
            mx = fmaxf(mx, y);
        }
        g_h[(size_t)gp * 512 + off + o] = mx;
    }
    atomicAdd(&g_sum[o], s);
    atomicAdd(&g_sumsq[o], ss);
}

__global__ void bn_apply_kernel(int off, int O, const float* __restrict__ gamma,
                                const float* __restrict__ beta, float cntinv) {
    int i = blockIdx.x * blockDim.x + threadIdx.x;
    if (i >= Bb * Nn * O) return;
    int o = i % O;
    int p = i / O;
    float mu = g_sum[o] * cntinv;
    float var = g_sumsq[o] * cntinv - mu * mu;
    float vin = g_h[(size_t)p * 512 + off + o];
    float y = (vin - mu) * rsqrtf(var + EPSF) * gamma[o] + beta[o];
    g_h[(size_t)p * 512 + off + o] = (y >= 0.f) ? y : 0.2f * y;
}

// ------------------------- conv5 stats + patch pool -------------------------
__global__ void col_stats_kernel() {
    int d = blockIdx.x * blockDim.x + threadIdx.x;
    int rows = (Bb * Nn) / 32;
    int m0 = blockIdx.y * rows;
    float s = 0.f, ss = 0.f;
    for (int m = m0; m < m0 + rows; m++) {
        float v = g_y5[(size_t)m * Dd + d];
        s += v;
        ss += v * v;
    }
    atomicAdd(&g_sum[d], s);
    atomicAdd(&g_sumsq[d], ss);
}

__global__ void patch_pool_kernel(const float* __restrict__ g5, const float* __restrict__ b5) {
    int bp = blockIdx.x;
    int b = bp / Pp, p = bp % Pp;
    float cntinv = 1.f / (float)(Bb * Nn);
    for (int d = threadIdx.x; d < Dd; d += 256) {
        float mu = g_sum[d] * cntinv;
        float var = g_sumsq[d] * cntinv - mu * mu;
        float sc = rsqrtf(var + EPSF) * g5[d];
        float bo = b5[d] - mu * sc;
        float mx = -1e30f;
        for (int s = 0; s < PSZ; s++) {
            float v = g_y5[((size_t)b * Nn + p * PSZ + s) * Dd + d];
            mx = fmaxf(mx, v);
        }
        float val = mx * sc + bo;
        val = (val >= 0.f) ? val : 0.2f * val;
        g_t[((size_t)b * LL + 1 + p) * Dd + d] = val;
    }
}

__global__ void cls_init_kernel(const float* __restrict__ cls) {
    int b = blockIdx.x;
    for (int d = threadIdx.x; d < Dd; d += 256)
        g_t[((size_t)b * LL) * Dd + d] = cls[d];
}

// ------------------------- transformer elementwise -------------------------
__global__ void add_pos_kernel(const float* __restrict__ pos) {
    int i = blockIdx.x * blockDim.x + threadIdx.x;
    if (i < Bb * LL * Dd) g_t[i] += pos[i];
}

__global__ void resid_kernel() {
    int i = blockIdx.x * blockDim.x + threadIdx.x;
    if (i < Bb * LL * Dd) g_t[i] += g_s2[i];
}

__global__ void ln_kernel(const float* __restrict__ in, float* __restrict__ out,
                          const float* __restrict__ gg, const float* __restrict__ bbv) {
    int row = blockIdx.x;
    const float* p = in + (size_t)row * Dd;
    float s = 0.f, ss = 0.f;
    for (int d = threadIdx.x; d < Dd; d += 256) {
        float v = p[d];
        s += v;
        ss += v * v;
    }
    __shared__ float red[2][8];
    int lane = threadIdx.x & 31, wid = threadIdx.x >> 5;
    for (int off = 16; off; off >>= 1) {
        s += __shfl_down_sync(0xffffffffu, s, off);
        ss += __shfl_down_sync(0xffffffffu, ss, off);
    }
    if (!lane) { red[0][wid] = s; red[1][wid] = ss; }
    __syncthreads();
    __shared__ float mu_s, rs_s;
    if (threadIdx.x == 0) {
        float S = 0.f, SS = 0.f;
        for (int i = 0; i < 8; i++) { S += red[0][i]; SS += red[1][i]; }
        float mu = S / Dd;
        float var = SS / Dd - mu * mu;
        mu_s = mu;
        rs_s = rsqrtf(var + EPSF);
    }
    __syncthreads();
    float mu = mu_s, r = rs_s;
    for (int d = threadIdx.x; d < Dd; d += 256)
        out[(size_t)row * Dd + d] = (p[d] - mu) * r * gg[d] + bbv[d];
}

// ------------------------- attention -------------------------
__global__ void attn_kernel() {
    extern __shared__ float sm[];
    float* qs = sm;
    float* ks = qs + 65 * 64;
    float* vs = ks + 65 * 65;
    float* pb = vs + 65 * 65;
    int b = blockIdx.x / HH, h = blockIdx.x % HH;
    int t = threadIdx.x, wid = t / 32, lane = t % 32;
    for (int i = t; i < 65 * 64; i += 256) {
        int l = i / 64, d = i % 64;
        size_t base = ((size_t)(b * LL + l)) * (3 * INNERD) + h * DHH + d;
        qs[l * 64 + d] = g_qkv[base];
        ks[l * 65 + d] = g_qkv[base + INNERD];
        vs[l * 65 + d] = g_qkv[base + 2 * INNERD];
    }
    __syncthreads();
    const float scale = 0.125f;
    for (int l = wid; l < LL; l += 8) {
        float lmax = -1e30f;
        for (int m = lane; m < LL; m += 32) {
            float acc = 0.f;
#pragma unroll 8
            for (int d = 0; d < 64; d++) acc += qs[l * 64 + d] * ks[m * 65 + d];
            acc *= scale;
            pb[wid * 66 + m] = acc;
            lmax = fmaxf(lmax, acc);
        }
        for (int off = 16; off; off >>= 1)
            lmax = fmaxf(lmax, __shfl_xor_sync(0xffffffffu, lmax, off));
        float lsum = 0.f;
        for (int m = lane; m < LL; m += 32) {
            float e = expf(pb[wid * 66 + m] - lmax);
            pb[wid * 66 + m] = e;
            lsum += e;
        }
        for (int off = 16; off; off >>= 1)
            lsum += __shfl_xor_sync(0xffffffffu, lsum, off);
        float inv = 1.f / lsum;
        for (int d = lane; d < 64; d += 32) {
            float acc = 0.f;
            for (int m = 0; m < LL; m++) acc += pb[wid * 66 + m] * vs[m * 65 + d];
            g_z[((size_t)(b * LL + l)) * INNERD + h * DHH + d] = acc * inv;
        }
    }
}

__global__ void copy_out_kernel(float* __restrict__ out) {
    int i = blockIdx.x * blockDim.x + threadIdx.x;
    if (i < Bb * Pp * Dd) {
        int d = i % Dd;
        int bp = i / Dd;
        int b = bp / Pp, p = bp % Pp;
        out[i] = g_t[((size_t)b * LL + 1 + p) * Dd + d];
    }
}

// ------------------------- host orchestration -------------------------
extern "C" void kernel_launch(void* const* d_in, const int* in_sizes, int n_in,
                              void* d_out, int out_size) {
    const float* x    = (const float*)d_in[0];
    const float* pos  = (const float*)d_in[1];
    const float* w1   = (const float*)d_in[2];
    const float* g1   = (const float*)d_in[3];
    const float* b1   = (const float*)d_in[4];
    const float* w2   = (const float*)d_in[5];
    const float* g2   = (const float*)d_in[6];
    const float* b2   = (const float*)d_in[7];
    const float* w3   = (const float*)d_in[8];
    const float* g3   = (const float*)d_in[9];
    const float* b3   = (const float*)d_in[10];
    const float* w4   = (const float*)d_in[11];
    const float* g4   = (const float*)d_in[12];
    const float* b4   = (const float*)d_in[13];
    const float* w5   = (const float*)d_in[14];
    const float* g5   = (const float*)d_in[15];
    const float* b5   = (const float*)d_in[16];
    const float* cls  = (const float*)d_in[17];
    const float* ln1g = (const float*)d_in[18];
    const float* ln1b = (const float*)d_in[19];
    const float* wqkv = (const float*)d_in[20];
    const float* wout = (const float*)d_in[21];
    const float* bout = (const float*)d_in[22];
    const float* ln2g = (const float*)d_in[23];
    const float* ln2b = (const float*)d_in[24];
    const float* wff1 = (const float*)d_in[25];
    const float* bff1 = (const float*)d_in[26];
    const float* wff2 = (const float*)d_in[27];
    const float* bff2 = (const float*)d_in[28];

    float *p_h, *p_u, *p_v, *p_wdiff, *p_y5, *p_t, *p_hn, *p_qkv, *p_z, *p_ff, *p_s2;
    cudaGetSymbolAddress((void**)&p_h, g_h);
    cudaGetSymbolAddress((void**)&p_u, g_u);
    cudaGetSymbolAddress((void**)&p_v, g_v);
    cudaGetSymbolAddress((void**)&p_wdiff, g_wdiff);
    cudaGetSymbolAddress((void**)&p_y5, g_y5);
    cudaGetSymbolAddress((void**)&p_t, g_t);
    cudaGetSymbolAddress((void**)&p_hn, g_hn);
    cudaGetSymbolAddress((void**)&p_qkv, g_qkv);
    cudaGetSymbolAddress((void**)&p_z, g_z);
    cudaGetSymbolAddress((void**)&p_ff, g_ff);
    cudaGetSymbolAddress((void**)&p_s2, g_s2);

    cudaFuncSetAttribute(knn_kernel, cudaFuncAttributeMaxDynamicSharedMemorySize,
                         16 * 128 * 4 + 16 * Nn * 4);
    cudaFuncSetAttribute(attn_kernel, cudaFuncAttributeMaxDynamicSharedMemorySize,
                         (65 * 64 + 2 * 65 * 65 + 8 * 66) * 4);
    cudaFuncSetAttribute(gemm_tf32_kernel<true>,
                         cudaFuncAttributeMaxDynamicSharedMemorySize, GEMM_SMEM);
    cudaFuncSetAttribute(gemm_tf32_kernel<false>,
                         cudaFuncAttributeMaxDynamicSharedMemorySize, GEMM_SMEM);

    auto gemm_nt = [&](const float* A, int lda, const float* Bp, int ldb, float* Cp,
                       int ldc, int M, int N, int K, const float* bias, int act) {
        dim3 g((N + BN - 1) / BN, (M + BM - 1) / BM);
        gemm_tf32_kernel<true><<<g, 256, GEMM_SMEM>>>(A, lda, Bp, ldb, Cp, ldc, M, N, K, bias, act);
    };
    auto gemm_nn = [&](const float* A, int lda, const float* Bp, int ldb, float* Cp,
                       int ldc, int M, int N, int K, const float* bias, int act) {
        dim3 g((N + BN - 1) / BN, (M + BM - 1) / BM);
        gemm_tf32_kernel<false><<<g, 256, GEMM_SMEM>>>(A, lda, Bp, ldb, Cp, ldc, M, N, K, bias, act);
    };

    auto edgeconv = [&](const float* xin, int ld, int C, int O, const float* w,
                        const float* gamma, const float* beta, int off) {
        dim3 tg(Nn / 32, (C + 31) / 32, Bb);
        transpose_kernel<<<tg, 256>>>(xin, ld, C);
        compute_xx_kernel<<<(Bb * Nn + 255) / 256, 256>>>(xin, ld, C);
        size_t smem = (size_t)16 * C * 4 + (size_t)16 * Nn * 4;
        knn_kernel<<<dim3(Nn / 16, Bb), 256, smem>>>(C);
        wdiff_kernel<<<(O * C + 255) / 256, 256>>>(w, O, C);
        gemm_nt(xin, ld, w, 2 * C, p_u, O, Bb * Nn, O, C, nullptr, 0);
        gemm_nt(xin, ld, p_wdiff, C, p_v, O, Bb * Nn, O, C, nullptr, 0);
        zero_stats_kernel<<<1, 1024>>>();
        edge_gather_kernel<<<Bb * Nn / 16, 256>>>(off, O);
        bn_apply_kernel<<<(Bb * Nn * O + 255) / 256, 256>>>(
            off, O, gamma, beta, 1.f / ((float)Bb * Nn * KK));
    };

    // ---- DGCNN encoder ----
    edgeconv(x, 3, 3, 64, w1, g1, b1, 0);
    edgeconv(p_h + 0, 512, 64, 64, w2, g2, b2, 64);
    edgeconv(p_h + 64, 512, 64, 128, w3, g3, b3, 128);
    edgeconv(p_h + 128, 512, 128, 256, w4, g4, b4, 256);

    // ---- conv5 + BN + leaky + patch max-pool ----
    gemm_nt(p_h, 512, w5, 512, p_y5, Dd, Bb * Nn, Dd, 512, nullptr, 0);
    zero_stats_kernel<<<1, 1024>>>();
    col_stats_kernel<<<dim3(Dd / 256, 32), 256>>>();
    patch_pool_kernel<<<Bb * Pp, 256>>>(g5, b5);
    cls_init_kernel<<<Bb, 256>>>(cls);

    // ---- transformer ----
    const int M = Bb * LL;        // 520
    const int nel = Bb * LL * Dd;
    for (int i = 0; i < DEPTHN; i++) {
        add_pos_kernel<<<(nel + 255) / 256, 256>>>(pos);
        ln_kernel<<<M, 256>>>(p_t, p_hn, ln1g + i * Dd, ln1b + i * Dd);
        gemm_nn(p_hn, Dd, wqkv + (size_t)i * Dd * 3 * INNERD, 3 * INNERD, p_qkv,
                3 * INNERD, M, 3 * INNERD, Dd, nullptr, 0);
        attn_kernel<<<Bb * HH, 256, (65 * 64 + 2 * 65 * 65 + 8 * 66) * 4>>>();
        gemm_nn(p_z, INNERD, wout + (size_t)i * INNERD * Dd, Dd, p_s2, Dd, M, Dd,
                INNERD, bout + i * Dd, 0);
        resid_kernel<<<(nel + 255) / 256, 256>>>();
        ln_kernel<<<M, 256>>>(p_t, p_hn, ln2g + i * Dd, ln2b + i * Dd);
        gemm_nn(p_hn, Dd, wff1 + (size_t)i * Dd * MLPD, MLPD, p_ff, MLPD, M, MLPD,
                Dd, bff1 + i * MLPD, 1 /*gelu*/);
        gemm_nn(p_ff, MLPD, wff2 + (size_t)i * MLPD * Dd, Dd, p_s2, Dd, M, Dd,
                MLPD, bff2 + i * Dd, 0);
        resid_kernel<<<(nel + 255) / 256, 256>>>();
    }

    copy_out_kernel<<<(Bb * Pp * Dd + 255) / 256, 256>>>((float*)d_out);
}

// round 7
// speedup vs baseline: 1.2891x; 1.2808x over previous
#include <cuda_runtime.h>
#include <math.h>
#include <stdint.h>

#define Bb     8
#define Nn     2048
#define KK     20
#define Pp     64
#define PSZ    32
#define Dd     1024
#define MLPD   2048
#define DEPTHN 6
#define HH     8
#define DHH    64
#define INNERD 512
#define LL     65
#define EPSF   1e-5f
#define KROWS  8

// ------------------------- device scratch -------------------------
__device__ float g_h[(size_t)Bb * Nn * 512];       // concat features [B*N][512]
__device__ float g_xcm[(size_t)Bb * 128 * Nn];     // channel-major copy for KNN
__device__ float g_u[(size_t)Bb * Nn * 256];
__device__ float g_v[(size_t)Bb * Nn * 256];
__device__ int   g_idx[(size_t)Bb * Nn * KK];
__device__ float g_xx[Bb * Nn];
__device__ float g_wdiff[256 * 128];
__device__ float g_sum[1024];
__device__ float g_sumsq[1024];
__device__ float g_y5[(size_t)Bb * Nn * Dd];       // conv5 output
__device__ float g_t[Bb * LL * Dd];                // transformer state
__device__ float g_hn[Bb * LL * Dd];
__device__ float g_qkv[Bb * LL * 3 * INNERD];
__device__ float g_z[Bb * LL * INNERD];
__device__ float g_ff[Bb * LL * MLPD];
__device__ float g_s2[Bb * LL * Dd];

// ------------------------- helpers -------------------------
__global__ void zero_stats_kernel() {
    int t = threadIdx.x;
    g_sum[t] = 0.f;
    g_sumsq[t] = 0.f;
}

// point-major [B*N][C] (row stride ld) -> channel-major g_xcm [B][C][N]
__global__ void transpose_kernel(const float* __restrict__ in, int ld, int C) {
    __shared__ float tile[32][33];
    int b = blockIdx.z;
    int n0 = blockIdx.x * 32, c0 = blockIdx.y * 32;
    int tx = threadIdx.x % 32, ty = threadIdx.x / 32;
    for (int i = ty; i < 32; i += 8) {
        int n = n0 + i, c = c0 + tx;
        tile[i][tx] = (c < C) ? in[((size_t)b * Nn + n) * ld + c] : 0.f;
    }
    __syncthreads();
    for (int i = ty; i < 32; i += 8) {
        int c = c0 + i, n = n0 + tx;
        if (c < C) g_xcm[((size_t)b * C + c) * Nn + n] = tile[tx][i];
    }
}

__global__ void compute_xx_kernel(const float* __restrict__ in, int ld, int C) {
    int i = blockIdx.x * blockDim.x + threadIdx.x;
    if (i < Bb * Nn) {
        const float* p = in + (size_t)i * ld;
        float s = 0.f;
        for (int c = 0; c < C; c++) s += p[c] * p[c];
        g_xx[i] = s;
    }
}

// ------------------------- fused KNN -------------------------
// grid (Nn/KROWS, Bb), 256 threads, dyn smem: xs[KROWS*C] + dist[KROWS*Nn]
// 8 rows/block -> 68KB smem -> 3 CTA/SM. Top-k: per-lane reg top-3 + warp argmax.
__global__ void knn_kernel(int C) {
    extern __shared__ float sm[];
    float* xs = sm;                    // [KROWS][C]
    float* dist = sm + KROWS * C;      // [KROWS][Nn]
    int b = blockIdx.y;
    int n0 = blockIdx.x * KROWS;
    int t = threadIdx.x;
    const float* xb = g_xcm + (size_t)b * C * Nn;

    for (int i = t; i < KROWS * C; i += 256) {
        int r = i % KROWS, c = i / KROWS;
        xs[r * C + c] = xb[(size_t)c * Nn + n0 + r];
    }
    __syncthreads();

    // distance tiles: per thread KROWS rows x 4 cols
    for (int half = 0; half < 2; half++) {
        int mb = half * 1024 + t;
        float acc[KROWS][4];
#pragma unroll
        for (int r = 0; r < KROWS; r++)
#pragma unroll
            for (int q = 0; q < 4; q++) acc[r][q] = 0.f;
        for (int c = 0; c < C; c++) {
            const float* col = xb + (size_t)c * Nn;
            float xm0 = col[mb];
            float xm1 = col[mb + 256];
            float xm2 = col[mb + 512];
            float xm3 = col[mb + 768];
#pragma unroll
            for (int r = 0; r < KROWS; r++) {
                float xr = xs[r * C + c];
                acc[r][0] += xr * xm0;
                acc[r][1] += xr * xm1;
                acc[r][2] += xr * xm2;
                acc[r][3] += xr * xm3;
            }
        }
#pragma unroll
        for (int q = 0; q < 4; q++) {
            float xxm = g_xx[b * Nn + mb + q * 256];
#pragma unroll
            for (int r = 0; r < KROWS; r++)
                dist[r * Nn + mb + q * 256] = 2.f * acc[r][q] - xxm;
        }
    }
    __syncthreads();

    // top-20: one warp per row. Per-lane register top-3 + 20 warp-argmax rounds.
    int wid = t >> 5, lane = t & 31;
    float* drow = dist + wid * Nn;
    int n = n0 + wid;

    float h1 = -1e30f, h2 = -1e30f, h3 = -1e30f;
    int i1 = 0x7fffffff, i2 = 0x7fffffff, i3 = 0x7fffffff;
#pragma unroll 4
    for (int s = 0; s < 64; s++) {
        int m = lane + s * 32;
        float v = drow[m];
        if (v > h3) {
            if (v > h2) {
                if (v > h1) { h3 = h2; i3 = i2; h2 = h1; i2 = i1; h1 = v; i1 = m; }
                else        { h3 = h2; i3 = i2; h2 = v;  i2 = m; }
            } else          { h3 = v;  i3 = m; }
        }
    }
    int nv = 3;
    for (int j = 0; j < KK; j++) {
        float bv = h1;
        int bi_ = i1;
        for (int off = 16; off; off >>= 1) {
            float ov = __shfl_down_sync(0xffffffffu, bv, off);
            int   oi = __shfl_down_sync(0xffffffffu, bi_, off);
            if (ov > bv || (ov == bv && oi < bi_)) { bv = ov; bi_ = oi; }
        }
        bv  = __shfl_sync(0xffffffffu, bv, 0);
        bi_ = __shfl_sync(0xffffffffu, bi_, 0);
        if (lane == 0) g_idx[((size_t)b * Nn + n) * KK + j] = bi_;
        if (i1 == bi_) {                 // indices globally unique -> unique winner
            drow[bi_] = -1e30f;          // exclude from future rescans (own residue only)
            h1 = h2; i1 = i2; h2 = h3; i2 = i3;
            h3 = -1e30f; i3 = 0x7fffffff;
            nv--;
            if (nv == 0) {               // lazy rescan of own 64 elements
                h1 = h2 = h3 = -1e30f;
                i1 = i2 = i3 = 0x7fffffff;
                for (int s = 0; s < 64; s++) {
                    int m = lane + s * 32;
                    float v = drow[m];
                    if (v > h3) {
                        if (v > h2) {
                            if (v > h1) { h3 = h2; i3 = i2; h2 = h1; i2 = i1; h1 = v; i1 = m; }
                            else        { h3 = h2; i3 = i2; h2 = v;  i2 = m; }
                        } else          { h3 = v;  i3 = m; }
                    }
                }
                nv = 3;
            }
        }
    }
}

// ------------------------- weight diff -------------------------
__global__ void wdiff_kernel(const float* __restrict__ w, int O, int C) {
    int i = blockIdx.x * blockDim.x + threadIdx.x;
    if (i < O * C) {
        int o = i / C, c = i % C;
        g_wdiff[i] = w[o * 2 * C + C + c] - w[o * 2 * C + c];
    }
}

// ------------------------- 3xTF32 tensor-core GEMM -------------------------
#define BM 64
#define BN 128
#define KB 32
#define LDA_S 36
#define LDB_S 133
#define GEMM_SMEM ((BM * LDA_S + KB * LDB_S) * 2 * 4)

__device__ __forceinline__ uint32_t f2tf32(float v) {
    uint32_t r;
    asm("cvt.rna.tf32.f32 %0, %1;" : "=r"(r) : "f"(v));
    return r;
}

__device__ __forceinline__ void mma_tf32(float* d, const uint32_t* a, const uint32_t* b) {
    asm volatile(
        "mma.sync.aligned.m16n8k8.row.col.f32.tf32.tf32.f32 "
        "{%0,%1,%2,%3}, {%4,%5,%6,%7}, {%8,%9}, {%0,%1,%2,%3};"
        : "+f"(d[0]), "+f"(d[1]), "+f"(d[2]), "+f"(d[3])
        : "r"(a[0]), "r"(a[1]), "r"(a[2]), "r"(a[3]), "r"(b[0]), "r"(b[1]));
}

template <bool TB>
__global__ __launch_bounds__(256, 2) void gemm_tf32_kernel(
    const float* __restrict__ A, int lda,
    const float* __restrict__ Bm, int ldb,
    float* __restrict__ Cm, int ldc,
    int M, int N, int K,
    const float* __restrict__ bias, int act) {
    extern __shared__ uint32_t smg[];
    uint32_t* AsH = smg;
    uint32_t* AsL = AsH + BM * LDA_S;
    uint32_t* BsH = AsL + BM * LDA_S;
    uint32_t* BsL = BsH + KB * LDB_S;
    int tid = threadIdx.x;
    int warp = tid >> 5, lane = tid & 31;
    int wm = warp >> 2;
    int wn = warp & 3;
    int g = lane >> 2, tg = lane & 3;
    int m0 = blockIdx.y * BM, n0 = blockIdx.x * BN;

    float acc[2][4][4];
#pragma unroll
    for (int mi = 0; mi < 2; mi++)
#pragma unroll
        for (int ni = 0; ni < 4; ni++)
#pragma unroll
            for (int q = 0; q < 4; q++) acc[mi][ni][q] = 0.f;

    for (int k0 = 0; k0 < K; k0 += KB) {
#pragma unroll
        for (int i = 0; i < 8; i++) {
            int e = tid + i * 256;
            int r = e >> 5, c = e & 31;
            int m = m0 + r, k = k0 + c;
            float v = (m < M && k < K) ? A[(size_t)m * lda + k] : 0.f;
            uint32_t hi = f2tf32(v);
            AsH[r * LDA_S + c] = hi;
            AsL[r * LDA_S + c] = f2tf32(v - __uint_as_float(hi));
        }
        if (TB) {
#pragma unroll
            for (int i = 0; i < 16; i++) {
                int e = tid + i * 256;
                int k = e & 31, n = e >> 5;
                int gn = n0 + n, gk = k0 + k;
                float v = (gn < N && gk < K) ? Bm[(size_t)gn * ldb + gk] : 0.f;
                uint32_t hi = f2tf32(v);
                BsH[k * LDB_S + n] = hi;
                BsL[k * LDB_S + n] = f2tf32(v - __uint_as_float(hi));
            }
        } else {
#pragma unroll
            for (int i = 0; i < 16; i++) {
                int e = tid + i * 256;
                int n = e & 127, k = e >> 7;
                int gn = n0 + n, gk = k0 + k;
                float v = (gn < N && gk < K) ? Bm[(size_t)gk * ldb + gn] : 0.f;
                uint32_t hi = f2tf32(v);
                BsH[k * LDB_S + n] = hi;
                BsL[k * LDB_S + n] = f2tf32(v - __uint_as_float(hi));
            }
        }
        __syncthreads();
#pragma unroll
        for (int ks = 0; ks < 4; ks++) {
            int kk = ks * 8;
            uint32_t aH[2][4], aL[2][4], bH[4][2], bL[4][2];
#pragma unroll
            for (int mi = 0; mi < 2; mi++) {
                int mb = wm * 32 + mi * 16;
                aH[mi][0] = AsH[(mb + g) * LDA_S + kk + tg];
                aH[mi][1] = AsH[(mb + g + 8) * LDA_S + kk + tg];
                aH[mi][2] = AsH[(mb + g) * LDA_S + kk + tg + 4];
                aH[mi][3] = AsH[(mb + g + 8) * LDA_S + kk + tg + 4];
                aL[mi][0] = AsL[(mb + g) * LDA_S + kk + tg];
                aL[mi][1] = AsL[(mb + g + 8) * LDA_S + kk + tg];
                aL[mi][2] = AsL[(mb + g) * LDA_S + kk + tg + 4];
                aL[mi][3] = AsL[(mb + g + 8) * LDA_S + kk + tg + 4];
            }
#pragma unroll
            for (int ni = 0; ni < 4; ni++) {
                int nb = wn * 32 + ni * 8;
                bH[ni][0] = BsH[(kk + tg) * LDB_S + nb + g];
                bH[ni][1] = BsH[(kk + tg + 4) * LDB_S + nb + g];
                bL[ni][0] = BsL[(kk + tg) * LDB_S + nb + g];
                bL[ni][1] = BsL[(kk + tg + 4) * LDB_S + nb + g];
            }
#pragma unroll
            for (int mi = 0; mi < 2; mi++)
#pragma unroll
                for (int ni = 0; ni < 4; ni++) {
                    mma_tf32(acc[mi][ni], aL[mi], bH[ni]);
                    mma_tf32(acc[mi][ni], aH[mi], bL[ni]);
                    mma_tf32(acc[mi][ni], aH[mi], bH[ni]);
                }
        }
        __syncthreads();
    }

#pragma unroll
    for (int mi = 0; mi < 2; mi++) {
#pragma unroll
        for (int ni = 0; ni < 4; ni++) {
            int col = n0 + wn * 32 + ni * 8 + tg * 2;
#pragma unroll
            for (int hf = 0; hf < 2; hf++) {
                int row = m0 + wm * 32 + mi * 16 + g + hf * 8;
                if (row >= M) continue;
#pragma unroll
                for (int q = 0; q < 2; q++) {
                    int c = col + q;
                    if (c >= N) continue;
                    float val = acc[mi][ni][hf * 2 + q];
                    if (bias) val += bias[c];
                    if (act == 1) val = 0.5f * val * (1.f + erff(val * 0.70710678118654752f));
                    Cm[(size_t)row * ldc + c] = val;
                }
            }
        }
    }
}

// ------------------------- edge gather + stats + max -------------------------
__global__ void edge_gather_kernel(int off, int O) {
    int t = threadIdx.x;
    int o = t % O;
    int nsub = t / O;
    int NPB = 256 / O;
    int base = blockIdx.x * 16;
    int b = base / Nn;
    float s = 0.f, ss = 0.f;
    int iters = 16 / NPB;
    for (int it = 0; it < iters; it++) {
        int gp = base + it * NPB + nsub;
        float vo = g_v[(size_t)gp * O + o];
        const int* ip = &g_idx[(size_t)gp * KK];
        float mx = -1e30f;
#pragma unroll
        for (int j = 0; j < KK; j++) {
            int mi = ip[j];
            float y = g_u[((size_t)b * Nn + mi) * O + o] + vo;
            s += y;
            ss += y * y;
            mx = fmaxf(mx, y);
        }
        g_h[(size_t)gp * 512 + off + o] = mx;
    }
    atomicAdd(&g_sum[o], s);
    atomicAdd(&g_sumsq[o], ss);
}

__global__ void bn_apply_kernel(int off, int O, const float* __restrict__ gamma,
                                const float* __restrict__ beta, float cntinv) {
    int i = blockIdx.x * blockDim.x + threadIdx.x;
    if (i >= Bb * Nn * O) return;
    int o = i % O;
    int p = i / O;
    float mu = g_sum[o] * cntinv;
    float var = g_sumsq[o] * cntinv - mu * mu;
    float vin = g_h[(size_t)p * 512 + off + o];
    float y = (vin - mu) * rsqrtf(var + EPSF) * gamma[o] + beta[o];
    g_h[(size_t)p * 512 + off + o] = (y >= 0.f) ? y : 0.2f * y;
}

// ------------------------- conv5 stats + patch pool -------------------------
__global__ void col_stats_kernel() {
    int d = blockIdx.x * blockDim.x + threadIdx.x;
    int rows = (Bb * Nn) / 32;
    int m0 = blockIdx.y * rows;
    float s = 0.f, ss = 0.f;
    for (int m = m0; m < m0 + rows; m++) {
        float v = g_y5[(size_t)m * Dd + d];
        s += v;
        ss += v * v;
    }
    atomicAdd(&g_sum[d], s);
    atomicAdd(&g_sumsq[d], ss);
}

__global__ void patch_pool_kernel(const float* __restrict__ g5, const float* __restrict__ b5) {
    int bp = blockIdx.x;
    int b = bp / Pp, p = bp % Pp;
    float cntinv = 1.f / (float)(Bb * Nn);
    for (int d = threadIdx.x; d < Dd; d += 256) {
        float mu = g_sum[d] * cntinv;
        float var = g_sumsq[d] * cntinv - mu * mu;
        float sc = rsqrtf(var + EPSF) * g5[d];
        float bo = b5[d] - mu * sc;
        float mx = -1e30f;
        for (int s = 0; s < PSZ; s++) {
            float v = g_y5[((size_t)b * Nn + p * PSZ + s) * Dd + d];
            mx = fmaxf(mx, v);
        }
        float val = mx * sc + bo;
        val = (val >= 0.f) ? val : 0.2f * val;
        g_t[((size_t)b * LL + 1 + p) * Dd + d] = val;
    }
}

__global__ void cls_init_kernel(const float* __restrict__ cls) {
    int b = blockIdx.x;
    for (int d = threadIdx.x; d < Dd; d += 256)
        g_t[((size_t)b * LL) * Dd + d] = cls[d];
}

// ------------------------- fused add(+add) + LayerNorm -------------------------
// t += a (+ b); hn = LN(t). 256 threads, one row (Dd=1024) per block.
__global__ void addln_kernel(float* __restrict__ tt, const float* __restrict__ a,
                             const float* __restrict__ b,
                             const float* __restrict__ gg, const float* __restrict__ bbv,
                             float* __restrict__ hn) {
    int row = blockIdx.x;
    size_t base = (size_t)row * Dd;
    float vals[4];
    float s = 0.f, ss = 0.f;
#pragma unroll
    for (int k = 0; k < 4; k++) {
        int d = threadIdx.x + k * 256;
        float v = tt[base + d] + a[base + d];
        if (b) v += b[base + d];
        vals[k] = v;
        s += v;
        ss += v * v;
        tt[base + d] = v;
    }
    __shared__ float red[2][8];
    int lane = threadIdx.x & 31, wid = threadIdx.x >> 5;
    for (int off = 16; off; off >>= 1) {
        s += __shfl_down_sync(0xffffffffu, s, off);
        ss += __shfl_down_sync(0xffffffffu, ss, off);
    }
    if (!lane) { red[0][wid] = s; red[1][wid] = ss; }
    __syncthreads();
    __shared__ float mu_s, rs_s;
    if (threadIdx.x == 0) {
        float S = 0.f, SS = 0.f;
        for (int i = 0; i < 8; i++) { S += red[0][i]; SS += red[1][i]; }
        float mu = S / Dd;
        float var = SS / Dd - mu * mu;
        mu_s = mu;
        rs_s = rsqrtf(var + EPSF);
    }
    __syncthreads();
    float mu = mu_s, r = rs_s;
#pragma unroll
    for (int k = 0; k < 4; k++) {
        int d = threadIdx.x + k * 256;
        hn[base + d] = (vals[k] - mu) * r * gg[d] + bbv[d];
    }
}

__global__ void resid_kernel() {
    int i = blockIdx.x * blockDim.x + threadIdx.x;
    if (i < Bb * LL * Dd) g_t[i] += g_s2[i];
}

// ------------------------- attention -------------------------
__global__ void attn_kernel() {
    extern __shared__ float sm[];
    float* qs = sm;
    float* ks = qs + 65 * 64;
    float* vs = ks + 65 * 65;
    float* pb = vs + 65 * 65;
    int b = blockIdx.x / HH, h = blockIdx.x % HH;
    int t = threadIdx.x, wid = t / 32, lane = t % 32;
    for (int i = t; i < 65 * 64; i += 256) {
        int l = i / 64, d = i % 64;
        size_t base = ((size_t)(b * LL + l)) * (3 * INNERD) + h * DHH + d;
        qs[l * 64 + d] = g_qkv[base];
        ks[l * 65 + d] = g_qkv[base + INNERD];
        vs[l * 65 + d] = g_qkv[base + 2 * INNERD];
    }
    __syncthreads();
    const float scale = 0.125f;
    for (int l = wid; l < LL; l += 8) {
        float lmax = -1e30f;
        for (int m = lane; m < LL; m += 32) {
            float acc = 0.f;
#pragma unroll 8
            for (int d = 0; d < 64; d++) acc += qs[l * 64 + d] * ks[m * 65 + d];
            acc *= scale;
            pb[wid * 66 + m] = acc;
            lmax = fmaxf(lmax, acc);
        }
        for (int off = 16; off; off >>= 1)
            lmax = fmaxf(lmax, __shfl_xor_sync(0xffffffffu, lmax, off));
        float lsum = 0.f;
        for (int m = lane; m < LL; m += 32) {
            float e = expf(pb[wid * 66 + m] - lmax);
            pb[wid * 66 + m] = e;
            lsum += e;
        }
        for (int off = 16; off; off >>= 1)
            lsum += __shfl_xor_sync(0xffffffffu, lsum, off);
        float inv = 1.f / lsum;
        for (int d = lane; d < 64; d += 32) {
            float acc = 0.f;
            for (int m = 0; m < LL; m++) acc += pb[wid * 66 + m] * vs[m * 65 + d];
            g_z[((size_t)(b * LL + l)) * INNERD + h * DHH + d] = acc * inv;
        }
    }
}

__global__ void copy_out_kernel(float* __restrict__ out) {
    int i = blockIdx.x * blockDim.x + threadIdx.x;
    if (i < Bb * Pp * Dd) {
        int d = i % Dd;
        int bp = i / Dd;
        int b = bp / Pp, p = bp % Pp;
        out[i] = g_t[((size_t)b * LL + 1 + p) * Dd + d];
    }
}

// ------------------------- host orchestration -------------------------
extern "C" void kernel_launch(void* const* d_in, const int* in_sizes, int n_in,
                              void* d_out, int out_size) {
    const float* x    = (const float*)d_in[0];
    const float* pos  = (const float*)d_in[1];
    const float* w1   = (const float*)d_in[2];
    const float* g1   = (const float*)d_in[3];
    const float* b1   = (const float*)d_in[4];
    const float* w2   = (const float*)d_in[5];
    const float* g2   = (const float*)d_in[6];
    const float* b2   = (const float*)d_in[7];
    const float* w3   = (const float*)d_in[8];
    const float* g3   = (const float*)d_in[9];
    const float* b3   = (const float*)d_in[10];
    const float* w4   = (const float*)d_in[11];
    const float* g4   = (const float*)d_in[12];
    const float* b4   = (const float*)d_in[13];
    const float* w5   = (const float*)d_in[14];
    const float* g5   = (const float*)d_in[15];
    const float* b5   = (const float*)d_in[16];
    const float* cls  = (const float*)d_in[17];
    const float* ln1g = (const float*)d_in[18];
    const float* ln1b = (const float*)d_in[19];
    const float* wqkv = (const float*)d_in[20];
    const float* wout = (const float*)d_in[21];
    const float* bout = (const float*)d_in[22];
    const float* ln2g = (const float*)d_in[23];
    const float* ln2b = (const float*)d_in[24];
    const float* wff1 = (const float*)d_in[25];
    const float* bff1 = (const float*)d_in[26];
    const float* wff2 = (const float*)d_in[27];
    const float* bff2 = (const float*)d_in[28];

    float *p_h, *p_u, *p_v, *p_wdiff, *p_y5, *p_t, *p_hn, *p_qkv, *p_z, *p_ff, *p_s2;
    cudaGetSymbolAddress((void**)&p_h, g_h);
    cudaGetSymbolAddress((void**)&p_u, g_u);
    cudaGetSymbolAddress((void**)&p_v, g_v);
    cudaGetSymbolAddress((void**)&p_wdiff, g_wdiff);
    cudaGetSymbolAddress((void**)&p_y5, g_y5);
    cudaGetSymbolAddress((void**)&p_t, g_t);
    cudaGetSymbolAddress((void**)&p_hn, g_hn);
    cudaGetSymbolAddress((void**)&p_qkv, g_qkv);
    cudaGetSymbolAddress((void**)&p_z, g_z);
    cudaGetSymbolAddress((void**)&p_ff, g_ff);
    cudaGetSymbolAddress((void**)&p_s2, g_s2);

    cudaFuncSetAttribute(knn_kernel, cudaFuncAttributeMaxDynamicSharedMemorySize,
                         KROWS * 128 * 4 + KROWS * Nn * 4);
    cudaFuncSetAttribute(attn_kernel, cudaFuncAttributeMaxDynamicSharedMemorySize,
                         (65 * 64 + 2 * 65 * 65 + 8 * 66) * 4);
    cudaFuncSetAttribute(gemm_tf32_kernel<true>,
                         cudaFuncAttributeMaxDynamicSharedMemorySize, GEMM_SMEM);
    cudaFuncSetAttribute(gemm_tf32_kernel<false>,
                         cudaFuncAttributeMaxDynamicSharedMemorySize, GEMM_SMEM);

    auto gemm_nt = [&](const float* A, int lda, const float* Bp, int ldb, float* Cp,
                       int ldc, int M, int N, int K, const float* bias, int act) {
        dim3 g((N + BN - 1) / BN, (M + BM - 1) / BM);
        gemm_tf32_kernel<true><<<g, 256, GEMM_SMEM>>>(A, lda, Bp, ldb, Cp, ldc, M, N, K, bias, act);
    };
    auto gemm_nn = [&](const float* A, int lda, const float* Bp, int ldb, float* Cp,
                       int ldc, int M, int N, int K, const float* bias, int act) {
        dim3 g((N + BN - 1) / BN, (M + BM - 1) / BM);
        gemm_tf32_kernel<false><<<g, 256, GEMM_SMEM>>>(A, lda, Bp, ldb, Cp, ldc, M, N, K, bias, act);
    };

    auto edgeconv = [&](const float* xin, int ld, int C, int O, const float* w,
                        const float* gamma, const float* beta, int off) {
        dim3 tg(Nn / 32, (C + 31) / 32, Bb);
        transpose_kernel<<<tg, 256>>>(xin, ld, C);
        compute_xx_kernel<<<(Bb * Nn + 255) / 256, 256>>>(xin, ld, C);
        wdiff_kernel<<<(O * C + 255) / 256, 256>>>(w, O, C);
        size_t smem = (size_t)KROWS * C * 4 + (size_t)KROWS * Nn * 4;
        knn_kernel<<<dim3(Nn / KROWS, Bb), 256, smem>>>(C);
        gemm_nt(xin, ld, w, 2 * C, p_u, O, Bb * Nn, O, C, nullptr, 0);
        gemm_nt(xin, ld, p_wdiff, C, p_v, O, Bb * Nn, O, C, nullptr, 0);
        zero_stats_kernel<<<1, 1024>>>();
        edge_gather_kernel<<<Bb * Nn / 16, 256>>>(off, O);
        bn_apply_kernel<<<(Bb * Nn * O + 255) / 256, 256>>>(
            off, O, gamma, beta, 1.f / ((float)Bb * Nn * KK));
    };

    // ---- DGCNN encoder ----
    edgeconv(x, 3, 3, 64, w1, g1, b1, 0);
    edgeconv(p_h + 0, 512, 64, 64, w2, g2, b2, 64);
    edgeconv(p_h + 64, 512, 64, 128, w3, g3, b3, 128);
    edgeconv(p_h + 128, 512, 128, 256, w4, g4, b4, 256);

    // ---- conv5 + BN + leaky + patch max-pool ----
    gemm_nt(p_h, 512, w5, 512, p_y5, Dd, Bb * Nn, Dd, 512, nullptr, 0);
    zero_stats_kernel<<<1, 1024>>>();
    col_stats_kernel<<<dim3(Dd / 256, 32), 256>>>();
    patch_pool_kernel<<<Bb * Pp, 256>>>(g5, b5);
    cls_init_kernel<<<Bb, 256>>>(cls);

    // ---- transformer ----
    const int M = Bb * LL;        // 520
    const int nel = Bb * LL * Dd;
    for (int i = 0; i < DEPTHN; i++) {
        if (i == 0)
            addln_kernel<<<M, 256>>>(p_t, pos, nullptr, ln1g, ln1b, p_hn);
        else
            addln_kernel<<<M, 256>>>(p_t, p_s2, pos, ln1g + i * Dd, ln1b + i * Dd, p_hn);
        gemm_nn(p_hn, Dd, wqkv + (size_t)i * Dd * 3 * INNERD, 3 * INNERD, p_qkv,
                3 * INNERD, M, 3 * INNERD, Dd, nullptr, 0);
        attn_kernel<<<Bb * HH, 256, (65 * 64 + 2 * 65 * 65 + 8 * 66) * 4>>>();
        gemm_nn(p_z, INNERD, wout + (size_t)i * INNERD * Dd, Dd, p_s2, Dd, M, Dd,
                INNERD, bout + i * Dd, 0);
        addln_kernel<<<M, 256>>>(p_t, p_s2, nullptr, ln2g + i * Dd, ln2b + i * Dd, p_hn);
        gemm_nn(p_hn, Dd, wff1 + (size_t)i * Dd * MLPD, MLPD, p_ff, MLPD, M, MLPD,
                Dd, bff1 + i * MLPD, 1 /*gelu*/);
        gemm_nn(p_ff, MLPD, wff2 + (size_t)i * MLPD * Dd, Dd, p_s2, Dd, M, Dd,
                MLPD, bff2 + i * Dd, 0);
    }
    resid_kernel<<<(nel + 255) / 256, 256>>>();

    copy_out_kernel<<<(Bb * Pp * Dd + 255) / 256, 256>>>((float*)d_out);
}